// round 1
// baseline (speedup 1.0000x reference)
#include <cuda_runtime.h>
#include <cstdint>

#define E_TOT  (256*4096)   // 1048576 edges
#define NNODE  (256*512)    // 131072 nodes
#define DHID   64
#define BNUM   256
#define EPB    4096
#define NPB    512
#define KKEEP  1024
#define KDROP  3072

// ---- scratch (device globals: allocation-free rule) ----
__device__ float g_AB[(size_t)NNODE * 512];   // [node][0:256]=A=h@W1top, [256:512]=B=h@W1bot
__device__ float g_scores[E_TOT];
__device__ unsigned char g_mask[NNODE];

// ---------------------------------------------------------------------------
// K0: zero the node mask (graph replays must be idempotent)
// ---------------------------------------------------------------------------
__global__ void k0_zero() {
    int i = blockIdx.x * blockDim.x + threadIdx.x;
    ((unsigned int*)g_mask)[i] = 0u;   // 131072 bytes = 32768 words
}

// ---------------------------------------------------------------------------
// K1: AB = h[131072x64] @ Wc[64x512]   (Wc = [W1top || W1bot])
// BM=64, BN=512 (full), K=64 (full). 256 threads, thread tile 8 rows x 16 cols
// (cols = 4*lane + 128*q). Packed f32x2 FMA for full-rate fp32.
// ---------------------------------------------------------------------------
__global__ void __launch_bounds__(256) k1_gemm(const float* __restrict__ hmat,
                                               const float* __restrict__ W1) {
    extern __shared__ float sm1[];
    float* Ws = sm1;               // [64][512]
    float* hs = sm1 + 64 * 512;    // [k][n] : [64][64]
    const int tid = threadIdx.x;
    const int rowbase = blockIdx.x * 64;

    // Load combined weight Wc[k][o]: o<256 -> W1[k][o], else W1[64+k][o-256]
    for (int i = tid; i < 64 * 128; i += 256) {
        int k  = i >> 7;
        int o4 = i & 127;
        int col = o4 * 4;
        const float* src = (col < 256) ? (W1 + k * 256 + col)
                                       : (W1 + (64 + k) * 256 + (col - 256));
        *(float4*)(Ws + k * 512 + col) = *(const float4*)src;
    }
    // Load h tile transposed: hs[k][n]
    for (int i = tid; i < 64 * 16; i += 256) {
        int n = i >> 4, k4 = i & 15;
        float4 v = *(const float4*)(hmat + (size_t)(rowbase + n) * 64 + k4 * 4);
        hs[(k4 * 4 + 0) * 64 + n] = v.x;
        hs[(k4 * 4 + 1) * 64 + n] = v.y;
        hs[(k4 * 4 + 2) * 64 + n] = v.z;
        hs[(k4 * 4 + 3) * 64 + n] = v.w;
    }
    __syncthreads();

    const int w = tid >> 5, l = tid & 31;
    const int r0 = w * 8;

    unsigned long long acc[8][8];  // [row][pair]; pair p of q-group: cols 128q+4l+2p'
    #pragma unroll
    for (int i = 0; i < 8; ++i)
        #pragma unroll
        for (int p = 0; p < 8; ++p) acc[i][p] = 0ull;

    #pragma unroll 4
    for (int k = 0; k < 64; ++k) {
        unsigned long long a2[8];
        #pragma unroll
        for (int i = 0; i < 8; ++i) {
            unsigned int au = __float_as_uint(hs[k * 64 + r0 + i]);  // warp-broadcast LDS
            asm("mov.b64 %0, {%1, %1};" : "=l"(a2[i]) : "r"(au));
        }
        unsigned long long b2v[8];
        #pragma unroll
        for (int q = 0; q < 4; ++q) {
            ulonglong2 bb = *(const ulonglong2*)(Ws + k * 512 + q * 128 + l * 4);
            b2v[q * 2] = bb.x; b2v[q * 2 + 1] = bb.y;
        }
        #pragma unroll
        for (int i = 0; i < 8; ++i)
            #pragma unroll
            for (int p = 0; p < 8; ++p)
                asm("fma.rn.f32x2 %0, %1, %2, %0;"
                    : "+l"(acc[i][p]) : "l"(a2[i]), "l"(b2v[p]));
    }

    #pragma unroll
    for (int i = 0; i < 8; ++i) {
        size_t rowoff = (size_t)(rowbase + r0 + i) * 512;
        #pragma unroll
        for (int q = 0; q < 4; ++q) {
            ulonglong2 v; v.x = acc[i][q * 2]; v.y = acc[i][q * 2 + 1];
            *(ulonglong2*)(g_AB + rowoff + q * 128 + l * 4) = v;
        }
    }
}

// ---------------------------------------------------------------------------
// K2: per-edge scores. One CTA per (batch, half): 512 threads, 4 edges each.
// Hidden dim processed in 8 chunks of 32; A(+b1 folded)/B chunk cached in SMEM
// with stride-33 padding (rows land in distinct banks mod 32).
// ---------------------------------------------------------------------------
__global__ void __launch_bounds__(512) k2_edges(const float* __restrict__ b1,
                                                const float* __restrict__ W2,
                                                const float* __restrict__ b2p,
                                                const int*   __restrict__ ei) {
    extern __shared__ float sm2[];
    float* As = sm2;              // [512][33]
    float* Bs = sm2 + 512 * 33;   // [512][33]
    const int tid  = threadIdx.x;
    const int b    = blockIdx.x >> 1;
    const int half = blockIdx.x & 1;
    const int ebase = b * EPB + half * 2048;

    int ra[4], ca[4];
    float accv[4] = {0.f, 0.f, 0.f, 0.f};
    #pragma unroll
    for (int i = 0; i < 4; ++i) {
        int e = ebase + tid + i * 512;
        ra[i] = (ei[e]         - b * NPB) * 33;
        ca[i] = (ei[E_TOT + e] - b * NPB) * 33;
    }
    const size_t nodebase = (size_t)b * NPB;

    for (int c = 0; c < 8; ++c) {
        __syncthreads();
        for (int idx = tid; idx < 512 * 32; idx += 512) {
            int n = idx >> 5, j = idx & 31;
            size_t goff = (nodebase + n) * 512 + c * 32 + j;
            As[n * 33 + j] = g_AB[goff] + b1[c * 32 + j];   // fold b1 into A
            Bs[n * 33 + j] = g_AB[goff + 256];
        }
        float w2r[32];
        #pragma unroll
        for (int j = 0; j < 32; ++j) w2r[j] = W2[c * 32 + j];
        __syncthreads();

        #pragma unroll
        for (int i = 0; i < 4; ++i) {
            float s = accv[i];
            const int rr = ra[i], cc = ca[i];
            #pragma unroll
            for (int j = 0; j < 32; ++j) {
                float hv = As[rr + j] + Bs[cc + j];
                hv = fmaxf(hv, 0.0f);
                s = fmaf(hv, w2r[j], s);
            }
            accv[i] = s;
        }
    }
    const float b2v = b2p[0];
    #pragma unroll
    for (int i = 0; i < 4; ++i)
        g_scores[ebase + tid + i * 512] = accv[i] + b2v;
}

// ---------------------------------------------------------------------------
// K3: per-batch full argsort (descending score, stable) via bitonic sort of
// 64-bit keys (~enc(score) << 32 | idx). Writes keep/drop weights + marks mask.
// ---------------------------------------------------------------------------
__global__ void __launch_bounds__(1024) k3_sort(const int* __restrict__ ei,
                                                float* __restrict__ out) {
    __shared__ unsigned long long keys[4096];
    const int b = blockIdx.x, tid = threadIdx.x;

    #pragma unroll
    for (int q = 0; q < 4; ++q) {
        int i = tid + q * 1024;
        unsigned int u = __float_as_uint(g_scores[b * EPB + i]);
        unsigned int enc = (u & 0x80000000u) ? ~u : (u | 0x80000000u); // ascending-sortable
        keys[i] = ((unsigned long long)(~enc) << 32) | (unsigned int)i; // asc key = desc score
    }
    __syncthreads();

    for (int k = 2; k <= 4096; k <<= 1) {
        for (int j = k >> 1; j > 0; j >>= 1) {
            #pragma unroll
            for (int q = 0; q < 4; ++q) {
                int i = tid + q * 1024;
                int ixj = i ^ j;
                if (ixj > i) {
                    unsigned long long a = keys[i], c = keys[ixj];
                    bool up = ((i & k) == 0);
                    if ((a > c) == up) { keys[i] = c; keys[ixj] = a; }
                }
            }
            __syncthreads();
        }
    }

    #pragma unroll
    for (int q = 0; q < 4; ++q) {
        int pos = tid + q * 1024;
        unsigned long long kv = keys[pos];
        unsigned int enc = ~(unsigned int)(kv >> 32);
        unsigned int bits = (enc & 0x80000000u) ? (enc ^ 0x80000000u) : ~enc;
        float s = __uint_as_float(bits);
        int idx = (int)(unsigned int)(kv & 0xFFFFFFFFu);
        if (pos < KKEEP) {
            out[BNUM * DHID + b * KKEEP + pos] = s;               // causal_edge_weight
            int g = b * EPB + idx;
            g_mask[ei[g]] = 1;
            g_mask[ei[E_TOT + g]] = 1;
        } else {
            out[BNUM * DHID + BNUM * KKEEP + b * KDROP + (pos - KKEEP)] = -s; // spu
        }
    }
}

// ---------------------------------------------------------------------------
// K4: causal_rep[b] = sum of h rows for masked nodes of batch b
// ---------------------------------------------------------------------------
__global__ void __launch_bounds__(256) k4_rep(const float* __restrict__ hmat,
                                              float* __restrict__ out) {
    __shared__ float red[4][64];
    const int b = blockIdx.x, tid = threadIdx.x;
    const int d = tid & 63, q = tid >> 6;
    const int nb = b * NPB;
    float s = 0.f;
    for (int n = q; n < NPB; n += 4) {
        if (g_mask[nb + n]) s += hmat[(size_t)(nb + n) * 64 + d];
    }
    red[q][d] = s;
    __syncthreads();
    if (tid < 64)
        out[b * 64 + tid] = red[0][tid] + red[1][tid] + red[2][tid] + red[3][tid];
}

// ---------------------------------------------------------------------------
extern "C" void kernel_launch(void* const* d_in, const int* in_sizes, int n_in,
                              void* d_out, int out_size) {
    const float* hmat = (const float*)d_in[0];
    const float* W1   = (const float*)d_in[1];
    const float* b1   = (const float*)d_in[2];
    const float* W2   = (const float*)d_in[3];
    const float* b2   = (const float*)d_in[4];
    const int*   ei   = (const int*)  d_in[5];
    float* out = (float*)d_out;

    const int smem1 = (64 * 512 + 64 * 64) * 4;   // 147456 B
    const int smem2 = 2 * 512 * 33 * 4;           // 135168 B
    cudaFuncSetAttribute(k1_gemm,  cudaFuncAttributeMaxDynamicSharedMemorySize, smem1);
    cudaFuncSetAttribute(k2_edges, cudaFuncAttributeMaxDynamicSharedMemorySize, smem2);

    k0_zero<<<32, 1024>>>();
    k1_gemm<<<NNODE / 64, 256, smem1>>>(hmat, W1);
    k2_edges<<<BNUM * 2, 512, smem2>>>(b1, W2, b2, ei);
    k3_sort<<<BNUM, 1024>>>(ei, out);
    k4_rep<<<BNUM, 256>>>(hmat, out);
}

// round 2
// speedup vs baseline: 1.5413x; 1.5413x over previous
#include <cuda_runtime.h>
#include <cstdint>

#define E_TOT  (256*4096)   // 1048576 edges
#define NNODE  (256*512)    // 131072 nodes
#define DHID   64
#define BNUM   256
#define EPB    4096
#define NPB    512
#define KKEEP  1024
#define KDROP  3072

// ---- scratch (device globals: allocation-free rule) ----
__device__ float g_AB[(size_t)NNODE * 512];   // [node][0:256]=A=h@W1top, [256:512]=B=h@W1bot
__device__ float g_scores[E_TOT];
__device__ unsigned char g_mask[NNODE];

// ---------------------------------------------------------------------------
// K0: zero the node mask (graph replays must be idempotent)
// ---------------------------------------------------------------------------
__global__ void k0_zero() {
    int i = blockIdx.x * blockDim.x + threadIdx.x;
    ((unsigned int*)g_mask)[i] = 0u;   // 131072 bytes = 32768 words
}

// ---------------------------------------------------------------------------
// K1: AB = h[131072x64] @ Wc[64x512]   (Wc = [W1top || W1bot])
// Packed f32x2 FMA, near the fp32x2 compute floor.
// ---------------------------------------------------------------------------
__global__ void __launch_bounds__(256) k1_gemm(const float* __restrict__ hmat,
                                               const float* __restrict__ W1) {
    extern __shared__ float sm1[];
    float* Ws = sm1;               // [64][512]
    float* hs = sm1 + 64 * 512;    // [k][n] : [64][64]
    const int tid = threadIdx.x;
    const int rowbase = blockIdx.x * 64;

    for (int i = tid; i < 64 * 128; i += 256) {
        int k  = i >> 7;
        int o4 = i & 127;
        int col = o4 * 4;
        const float* src = (col < 256) ? (W1 + k * 256 + col)
                                       : (W1 + (64 + k) * 256 + (col - 256));
        *(float4*)(Ws + k * 512 + col) = *(const float4*)src;
    }
    for (int i = tid; i < 64 * 16; i += 256) {
        int n = i >> 4, k4 = i & 15;
        float4 v = *(const float4*)(hmat + (size_t)(rowbase + n) * 64 + k4 * 4);
        hs[(k4 * 4 + 0) * 64 + n] = v.x;
        hs[(k4 * 4 + 1) * 64 + n] = v.y;
        hs[(k4 * 4 + 2) * 64 + n] = v.z;
        hs[(k4 * 4 + 3) * 64 + n] = v.w;
    }
    __syncthreads();

    const int w = tid >> 5, l = tid & 31;
    const int r0 = w * 8;

    unsigned long long acc[8][8];
    #pragma unroll
    for (int i = 0; i < 8; ++i)
        #pragma unroll
        for (int p = 0; p < 8; ++p) acc[i][p] = 0ull;

    #pragma unroll 4
    for (int k = 0; k < 64; ++k) {
        unsigned long long a2[8];
        #pragma unroll
        for (int i = 0; i < 8; ++i) {
            unsigned int au = __float_as_uint(hs[k * 64 + r0 + i]);
            asm("mov.b64 %0, {%1, %1};" : "=l"(a2[i]) : "r"(au));
        }
        unsigned long long b2v[8];
        #pragma unroll
        for (int q = 0; q < 4; ++q) {
            ulonglong2 bb = *(const ulonglong2*)(Ws + k * 512 + q * 128 + l * 4);
            b2v[q * 2] = bb.x; b2v[q * 2 + 1] = bb.y;
        }
        #pragma unroll
        for (int i = 0; i < 8; ++i)
            #pragma unroll
            for (int p = 0; p < 8; ++p)
                asm("fma.rn.f32x2 %0, %1, %2, %0;"
                    : "+l"(acc[i][p]) : "l"(a2[i]), "l"(b2v[p]));
    }

    #pragma unroll
    for (int i = 0; i < 8; ++i) {
        size_t rowoff = (size_t)(rowbase + r0 + i) * 512;
        #pragma unroll
        for (int q = 0; q < 4; ++q) {
            ulonglong2 v; v.x = acc[i][q * 2]; v.y = acc[i][q * 2 + 1];
            *(ulonglong2*)(g_AB + rowoff + q * 128 + l * 4) = v;
        }
    }
}

// ---------------------------------------------------------------------------
// K2: per-edge scores. ONE CTA per batch (g_AB read once). 512 threads,
// 8 edges each, hidden chunks of 32 with pad-36 rows (16B aligned, LDS.128).
// ---------------------------------------------------------------------------
__global__ void __launch_bounds__(512) k2_edges(const float* __restrict__ b1,
                                                const float* __restrict__ W2,
                                                const float* __restrict__ b2p,
                                                const int*   __restrict__ ei) {
    extern __shared__ float sm2[];
    float* As = sm2;              // [512][36]
    float* Bs = sm2 + 512 * 36;   // [512][36]
    __shared__ float w2s[256];
    const int tid  = threadIdx.x;
    const int b    = blockIdx.x;
    const int ebase = b * EPB;
    const size_t nb = (size_t)b * NPB;

    if (tid < 64) *(float4*)(w2s + tid * 4) = *(const float4*)(W2 + tid * 4);

    int rcl[8], ccl[8];
    float acc[8];
    #pragma unroll
    for (int i = 0; i < 8; ++i) {
        int e = ebase + tid + i * 512;
        rcl[i] = (ei[e]         - b * NPB) * 36;
        ccl[i] = (ei[E_TOT + e] - b * NPB) * 36;
        acc[i] = 0.f;
    }

    for (int c = 0; c < 8; ++c) {
        __syncthreads();
        #pragma unroll
        for (int t = 0; t < 8; ++t) {
            int idx = tid + t * 512;          // 0..4095
            int n = idx >> 3, g = idx & 7;
            const float* gp = g_AB + (nb + n) * 512 + c * 32 + g * 4;
            float4 va = *(const float4*)gp;
            float4 vb = *(const float4*)(gp + 256);
            float4 bv = *(const float4*)(b1 + c * 32 + g * 4);
            va.x += bv.x; va.y += bv.y; va.z += bv.z; va.w += bv.w;
            *(float4*)(As + n * 36 + g * 4) = va;
            *(float4*)(Bs + n * 36 + g * 4) = vb;
        }
        __syncthreads();

        float w2r[32];
        #pragma unroll
        for (int g = 0; g < 8; ++g)
            *(float4*)(w2r + g * 4) = *(const float4*)(w2s + c * 32 + g * 4);

        #pragma unroll
        for (int i = 0; i < 8; ++i) {
            float s = acc[i];
            const float* Ap = As + rcl[i];
            const float* Bp = Bs + ccl[i];
            #pragma unroll
            for (int g = 0; g < 8; ++g) {
                float4 a4 = *(const float4*)(Ap + g * 4);
                float4 b4 = *(const float4*)(Bp + g * 4);
                s = fmaf(fmaxf(a4.x + b4.x, 0.f), w2r[g * 4 + 0], s);
                s = fmaf(fmaxf(a4.y + b4.y, 0.f), w2r[g * 4 + 1], s);
                s = fmaf(fmaxf(a4.z + b4.z, 0.f), w2r[g * 4 + 2], s);
                s = fmaf(fmaxf(a4.w + b4.w, 0.f), w2r[g * 4 + 3], s);
            }
            acc[i] = s;
        }
    }
    const float b2v = b2p[0];
    #pragma unroll
    for (int i = 0; i < 8; ++i)
        g_scores[ebase + tid + i * 512] = acc[i] + b2v;
}

// ---------------------------------------------------------------------------
// K3: hybrid bitonic argsort (4096 keys, 4/thread in registers).
// j>=128: SMEM;  4<=j<=64: shfl;  j in {1,2}: in-thread.
// Key: (~enc(score))<<32 | idx  -> ascending sort == stable descending score.
// ---------------------------------------------------------------------------
__global__ void __launch_bounds__(1024) k3_sort(const int* __restrict__ ei,
                                                float* __restrict__ out) {
    __shared__ unsigned long long sk[4096];
    const int b = blockIdx.x, tid = threadIdx.x;

    unsigned long long key[4];
    float4 sc = *(const float4*)(g_scores + b * EPB + tid * 4);
    float sv[4] = {sc.x, sc.y, sc.z, sc.w};
    #pragma unroll
    for (int r = 0; r < 4; ++r) {
        unsigned int u = __float_as_uint(sv[r]);
        unsigned int enc = (u & 0x80000000u) ? ~u : (u | 0x80000000u);
        key[r] = ((unsigned long long)(~enc) << 32) | (unsigned int)(tid * 4 + r);
    }

    for (int k = 2; k <= 4096; k <<= 1) {
        int j = k >> 1;
        // --- SMEM stages ---
        for (; j >= 128; j >>= 1) {
            #pragma unroll
            for (int r = 0; r < 4; ++r) sk[tid * 4 + r] = key[r];
            __syncthreads();
            #pragma unroll
            for (int r = 0; r < 4; ++r) {
                int i = tid * 4 + r;
                unsigned long long pk = sk[i ^ j];
                bool up = ((i & k) == 0);
                bool lo = ((i & j) == 0);
                unsigned long long mn = key[r] < pk ? key[r] : pk;
                unsigned long long mx = key[r] < pk ? pk : key[r];
                key[r] = (lo == up) ? mn : mx;
            }
            __syncthreads();
        }
        // --- shfl stages ---
        for (; j >= 4; j >>= 1) {
            int lm = j >> 2;
            #pragma unroll
            for (int r = 0; r < 4; ++r) {
                unsigned long long pk = __shfl_xor_sync(0xffffffffu, key[r], lm);
                int i = tid * 4 + r;
                bool up = ((i & k) == 0);
                bool lo = ((i & j) == 0);
                unsigned long long mn = key[r] < pk ? key[r] : pk;
                unsigned long long mx = key[r] < pk ? pk : key[r];
                key[r] = (lo == up) ? mn : mx;
            }
        }
        // --- j == 2 ---
        if (k >= 4) {
            #pragma unroll
            for (int r = 0; r < 2; ++r) {
                int i = tid * 4 + r;
                bool up = ((i & k) == 0);
                unsigned long long a = key[r], c2 = key[r + 2];
                unsigned long long mn = a < c2 ? a : c2;
                unsigned long long mx = a < c2 ? c2 : a;
                key[r]     = up ? mn : mx;
                key[r + 2] = up ? mx : mn;
            }
        }
        // --- j == 1 ---
        #pragma unroll
        for (int p = 0; p < 2; ++p) {
            int r0 = p * 2;
            int i = tid * 4 + r0;
            bool up = ((i & k) == 0);
            unsigned long long a = key[r0], c2 = key[r0 + 1];
            unsigned long long mn = a < c2 ? a : c2;
            unsigned long long mx = a < c2 ? c2 : a;
            key[r0]     = up ? mn : mx;
            key[r0 + 1] = up ? mx : mn;
        }
    }

    const int obase_keep = BNUM * DHID;
    const int obase_spu  = obase_keep + BNUM * KKEEP;
    #pragma unroll
    for (int r = 0; r < 4; ++r) {
        int pos = tid * 4 + r;
        unsigned long long kv = key[r];
        unsigned int enc = ~(unsigned int)(kv >> 32);
        unsigned int bits = (enc & 0x80000000u) ? (enc ^ 0x80000000u) : ~enc;
        float s = __uint_as_float(bits);
        int idx = (int)(unsigned int)(kv & 0xFFFFFFFFu);
        if (pos < KKEEP) {
            out[obase_keep + b * KKEEP + pos] = s;
            int g = b * EPB + idx;
            g_mask[ei[g]] = 1;
            g_mask[ei[E_TOT + g]] = 1;
        } else {
            out[obase_spu + b * KDROP + (pos - KKEEP)] = -s;
        }
    }
}

// ---------------------------------------------------------------------------
// K4: causal_rep[b] = sum of h rows for masked nodes of batch b
// ---------------------------------------------------------------------------
__global__ void __launch_bounds__(256) k4_rep(const float* __restrict__ hmat,
                                              float* __restrict__ out) {
    __shared__ float red[4][64];
    const int b = blockIdx.x, tid = threadIdx.x;
    const int d = tid & 63, q = tid >> 6;
    const int nb = b * NPB;
    float s = 0.f;
    for (int n = q; n < NPB; n += 4) {
        if (g_mask[nb + n]) s += hmat[(size_t)(nb + n) * 64 + d];
    }
    red[q][d] = s;
    __syncthreads();
    if (tid < 64)
        out[b * 64 + tid] = red[0][tid] + red[1][tid] + red[2][tid] + red[3][tid];
}

// ---------------------------------------------------------------------------
extern "C" void kernel_launch(void* const* d_in, const int* in_sizes, int n_in,
                              void* d_out, int out_size) {
    const float* hmat = (const float*)d_in[0];
    const float* W1   = (const float*)d_in[1];
    const float* b1   = (const float*)d_in[2];
    const float* W2   = (const float*)d_in[3];
    const float* b2   = (const float*)d_in[4];
    const int*   ei   = (const int*)  d_in[5];
    float* out = (float*)d_out;

    const int smem1 = (64 * 512 + 64 * 64) * 4;   // 147456 B
    const int smem2 = 2 * 512 * 36 * 4;           // 147456 B
    cudaFuncSetAttribute(k1_gemm,  cudaFuncAttributeMaxDynamicSharedMemorySize, smem1);
    cudaFuncSetAttribute(k2_edges, cudaFuncAttributeMaxDynamicSharedMemorySize, smem2);

    k0_zero<<<32, 1024>>>();
    k1_gemm<<<NNODE / 64, 256, smem1>>>(hmat, W1);
    k2_edges<<<BNUM, 512, smem2>>>(b1, W2, b2, ei);
    k3_sort<<<BNUM, 1024>>>(ei, out);
    k4_rep<<<BNUM, 256>>>(hmat, out);
}